// round 6
// baseline (speedup 1.0000x reference)
#include <cuda_runtime.h>
#include <cuda_bf16.h>
#include <math.h>

// ---------------- Problem dims ----------------
#define BB 512
#define TT 512
#define VV 50000
#define EE 100
#define HH 40

typedef unsigned long long u64;

// ---------------- f32x2 packed helpers ----------------
__device__ __forceinline__ u64 f2u2(float x, float y) {
    u64 u; asm("mov.b64 %0, {%1,%2};" : "=l"(u) : "f"(x), "f"(y)); return u;
}
__device__ __forceinline__ u64 fma2(u64 a, u64 b, u64 c) {
    u64 d; asm("fma.rn.f32x2 %0, %1, %2, %3;" : "=l"(d) : "l"(a), "l"(b), "l"(c)); return d;
}
__device__ __forceinline__ float2 u2f2(u64 u) {
    float lo, hi; asm("mov.b64 {%0,%1}, %2;" : "=f"(lo), "=f"(hi) : "l"(u));
    return make_float2(lo, hi);
}

__device__ __forceinline__ float sigf(float x) {
    return __fdividef(1.f, 1.f + __expf(-x));
}
__device__ __forceinline__ float tanh_fast(float x) {
    float a = fminf(fmaxf(-2.f * x, -80.f), 80.f);
    float e = __expf(a);
    return __fdividef(1.f - e, 1.f + e);
}

// ---------------- Device scratch ----------------
__device__ __align__(16) float g_embW0[VV * 240];            // layer0 input gates per vocab id
__device__ __align__(16) float g_out0[BB * TT * 80];         // layer0 out, [b][t][fwd40|bwd40]
__device__ __align__(16) float g_gx1[(size_t)BB * TT * 240]; // layer1 precomputed input gates
__device__ __align__(16) float g_Wih0T[EE * 240];
__device__ __align__(16) float g_bih0cat[240];
__device__ __align__(16) float g_Wih1T[80 * 240];
__device__ __align__(16) float g_bih1cat[240];
// 4-output gate-owner pack: [dir][f(0..119)][k2(0..19)] u64 pairs
__device__ __align__(16) float g_Whh0P4[2 * 120 * 20 * 2];
__device__ __align__(16) float g_Whh1P4[2 * 120 * 20 * 2];
__device__ __align__(16) float g_fc1WT[320 * 128];
__device__ float g_hf0[BB * HH], g_hb0[BB * HH], g_hf1[BB * HH], g_hb1[BB * HH];
__device__ float g_avgp[BB * 80], g_maxp[BB * 80];
__device__ int g_perm[BB];

// ---------------- Prep: transpose / pack all weights ----------------
__global__ void prep_weights(
    const float* __restrict__ Wih0f, const float* __restrict__ Whh0f,
    const float* __restrict__ bih0f,
    const float* __restrict__ Wih0b, const float* __restrict__ Whh0b,
    const float* __restrict__ bih0b,
    const float* __restrict__ Wih1f, const float* __restrict__ Whh1f,
    const float* __restrict__ bih1f,
    const float* __restrict__ Wih1b, const float* __restrict__ Whh1b,
    const float* __restrict__ bih1b,
    const float* __restrict__ fc1_W)
{
    int g = blockIdx.x * blockDim.x + threadIdx.x;
    int NT = gridDim.x * blockDim.x;
    for (int i = g; i < EE * 240; i += NT) {
        int k = i / 240, j = i % 240;
        g_Wih0T[i] = (j < 120) ? Wih0f[j * EE + k] : Wih0b[(j - 120) * EE + k];
    }
    for (int i = g; i < 80 * 240; i += NT) {
        int k = i / 240, j = i % 240;
        g_Wih1T[i] = (j < 120) ? Wih1f[j * 80 + k] : Wih1b[(j - 120) * 80 + k];
    }
    for (int i = g; i < 240; i += NT) {
        g_bih0cat[i] = (i < 120) ? bih0f[i] : bih0b[i - 120];
        g_bih1cat[i] = (i < 120) ? bih1f[i] : bih1b[i - 120];
    }
    // P4 packs: idx = ((dir*120 + f)*20 + k2)*2 + c  ->  Whh_dir[f*40 + 2*k2 + c]
    for (int i = g; i < 2 * 120 * 20 * 2; i += NT) {
        int c = i & 1;
        int t = i >> 1;
        int k2 = t % 20;
        int f = (t / 20) % 120;
        int dir = t / 2400;
        int src = f * 40 + 2 * k2 + c;
        g_Whh0P4[i] = (dir ? Whh0b : Whh0f)[src];
        g_Whh1P4[i] = (dir ? Whh1b : Whh1f)[src];
    }
    for (int i = g; i < 320 * 128; i += NT) {
        int k = i / 128, q = i % 128;
        g_fc1WT[i] = fc1_W[q * 320 + k];
    }
}

// ---------------- Length sort (descending) for load balance ----------------
__global__ void sort_kernel(const int* __restrict__ lens)
{
    __shared__ int L[BB];
    int b = threadIdx.x;
    int lb = lens[b];
    L[b] = lb;
    __syncthreads();
    int r = 0;
    #pragma unroll 8
    for (int i = 0; i < BB; i++) {
        int li = L[i];
        r += (li > lb) || (li == lb && i < b);
    }
    g_perm[r] = b;
}

// ---------------- embW GEMM: [50000,100] x [100,240] + bias ----------------
__global__ void __launch_bounds__(256) embw_kernel(const float* __restrict__ emb)
{
    int j = threadIdx.x;
    int v0 = blockIdx.x * 64;
    int rows = VV - v0; if (rows > 64) rows = 64;
    __shared__ __align__(16) float A_s[20][68];

    u64 acc[32];
    float bias = (j < 240) ? g_bih0cat[j] : 0.f;
    u64 binit = f2u2(bias, bias);
    #pragma unroll
    for (int i = 0; i < 32; i++) acc[i] = binit;

    for (int k0 = 0; k0 < EE; k0 += 20) {
        __syncthreads();
        for (int idx = threadIdx.x; idx < 64 * 20; idx += 256) {
            int r = idx / 20, k = idx % 20;
            A_s[k][r] = (r < rows) ? emb[(size_t)(v0 + r) * EE + k0 + k] : 0.f;
        }
        __syncthreads();
        if (j < 240) {
            #pragma unroll
            for (int k = 0; k < 20; k++) {
                float wv = g_Wih0T[(k0 + k) * 240 + j];
                u64 ww = f2u2(wv, wv);
                const ulonglong2* ap = (const ulonglong2*)(&A_s[k][0]);
                #pragma unroll
                for (int p = 0; p < 16; p++) {
                    ulonglong2 a = ap[p];
                    acc[2 * p + 0] = fma2(a.x, ww, acc[2 * p + 0]);
                    acc[2 * p + 1] = fma2(a.y, ww, acc[2 * p + 1]);
                }
            }
        }
    }
    if (j < 240) {
        #pragma unroll
        for (int i = 0; i < 32; i++) {
            float2 v = u2f2(acc[i]);
            int r = 2 * i;
            if (r < rows)     g_embW0[(size_t)(v0 + r) * 240 + j] = v.x;
            if (r + 1 < rows) g_embW0[(size_t)(v0 + r + 1) * 240 + j] = v.y;
        }
    }
}

// ---------------- gx1 GEMM: [valid rows,80] x [80,240] + bias ----------------
__global__ void __launch_bounds__(256) gx1_kernel(const int* __restrict__ lens)
{
    int b = blockIdx.x;
    int t0 = blockIdx.y * 64;
    int len = lens[b];
    if (t0 >= len) return;
    int rows = len - t0; if (rows > 64) rows = 64;
    int tid = threadIdx.x;
    __shared__ __align__(16) float Xt[80][68];   // [k][r]

    const float4* xb = (const float4*)(g_out0 + ((size_t)b * TT + t0) * 80);
    for (int idx = tid; idx < 64 * 20; idx += 256) {
        int r = idx / 20, c4 = idx % 20;
        float4 v = (r < rows) ? xb[r * 20 + c4] : make_float4(0.f, 0.f, 0.f, 0.f);
        Xt[4 * c4 + 0][r] = v.x;
        Xt[4 * c4 + 1][r] = v.y;
        Xt[4 * c4 + 2][r] = v.z;
        Xt[4 * c4 + 3][r] = v.w;
    }
    __syncthreads();

    int j = tid;
    if (j < 240) {
        u64 acc[32];
        float bias = g_bih1cat[j];
        u64 binit = f2u2(bias, bias);
        #pragma unroll
        for (int i = 0; i < 32; i++) acc[i] = binit;

        #pragma unroll 4
        for (int k = 0; k < 80; k++) {
            float wv = g_Wih1T[k * 240 + j];
            u64 ww = f2u2(wv, wv);
            const ulonglong2* ap = (const ulonglong2*)(&Xt[k][0]);
            #pragma unroll
            for (int p = 0; p < 16; p++) {
                ulonglong2 a = ap[p];
                acc[2 * p + 0] = fma2(a.x, ww, acc[2 * p + 0]);
                acc[2 * p + 1] = fma2(a.y, ww, acc[2 * p + 1]);
            }
        }
        float* ob = g_gx1 + ((size_t)b * TT + t0) * 240 + j;
        #pragma unroll
        for (int i = 0; i < 32; i++) {
            float2 v = u2f2(acc[i]);
            int r = 2 * i;
            if (r < rows)     ob[(size_t)r * 240] = v.x;
            if (r + 1 < rows) ob[(size_t)(r + 1) * 240] = v.y;
        }
    }
}

// ---------------- Layer 0: one warp per (batch,dir), no barriers ----------------
// grid 148 x 128 threads = 592 warps; warp j<512 runs combos j and 1023-j (len-sorted,
// constant-sum pairing). Lane l owns flat gate rows {l, l+32, l+64, l+96} for the dot,
// and unit l (+ unit 32+l for l<8) for activations/state.
__global__ void __launch_bounds__(128) gru_layer0(
    const int* __restrict__ text, const int* __restrict__ lens,
    const float* __restrict__ bhh0f, const float* __restrict__ bhh0b)
{
    int wid = threadIdx.x >> 5, lane = threadIdx.x & 31;
    int wgid = blockIdx.x * 4 + wid;
    __shared__ int toks_s[4][TT];
    __shared__ float dots_s[4][128];
    __shared__ __align__(16) float h_s[4][48];
    if (wgid >= 512) return;
    int* toks = toks_s[wid];
    float* dots = dots_s[wid];
    float* hsm = h_s[wid];

    for (int slot = 0; slot < 2; slot++) {
        int c = slot ? (1023 - wgid) : wgid;
        int b = g_perm[c >> 1];
        int dir = c & 1;
        int len = lens[b];

        for (int i = lane; i < len; i += 32) toks[i] = text[b * TT + i];

        u64 w[4][20];
        float bb[4];
        const u64* wp = (const u64*)g_Whh0P4 + (size_t)dir * 120 * 20;
        const float* bhh = dir ? bhh0b : bhh0f;
        #pragma unroll
        for (int m = 0; m < 4; m++) {
            int f = lane + 32 * m;
            if (f < 120) {
                const u64* wf = wp + f * 20;
                #pragma unroll
                for (int k2 = 0; k2 < 20; k2++) w[m][k2] = wf[k2];
                bb[m] = bhh[f];
            } else {
                #pragma unroll
                for (int k2 = 0; k2 < 20; k2++) w[m][k2] = 0ull;
                bb[m] = 0.f;
            }
        }
        hsm[lane] = 0.f;
        if (lane < 16) hsm[32 + lane] = 0.f;
        __syncwarp();

        int t0 = dir ? (len - 1) : 0;
        int td = dir ? -1 : 1;
        const float* embW = g_embW0 + dir * 120;
        int u0 = lane;
        int u1 = 32 + lane;     // valid for lane < 8
        bool two = (lane < 8);

        float a0r=0,a0z=0,a0n=0,a1r=0,a1z=0,a1n=0;
        float c0r=0,c0z=0,c0n=0,c1r=0,c1z=0,c1n=0;
        {
            const float* e0 = embW + (size_t)toks[t0] * 240;
            a0r = e0[u0]; a0z = e0[40 + u0]; a0n = e0[80 + u0];
            if (two) { c0r = e0[u1]; c0z = e0[40 + u1]; c0n = e0[80 + u1]; }
            if (len > 1) {
                const float* e1 = embW + (size_t)toks[t0 + td] * 240;
                a1r = e1[u0]; a1z = e1[40 + u0]; a1n = e1[80 + u0];
                if (two) { c1r = e1[u1]; c1z = e1[40 + u1]; c1n = e1[80 + u1]; }
            }
        }
        float h0 = 0.f, h1 = 0.f;
        float* outb = g_out0 + ((size_t)b * TT + t0) * 80 + dir * 40;
        long ostep = (long)td * 80;

        for (int s = 0; s < len; s++) {
            float a2r=0,a2z=0,a2n=0,c2r=0,c2z=0,c2n=0;
            if (s + 2 < len) {
                const float* e2 = embW + (size_t)toks[t0 + (s + 2) * td] * 240;
                a2r = e2[u0]; a2z = e2[40 + u0]; a2n = e2[80 + u0];
                if (two) { c2r = e2[u1]; c2z = e2[40 + u1]; c2n = e2[80 + u1]; }
            }
            // dot phase: 4 outputs per lane
            u64 ac0 = f2u2(bb[0], 0.f), ac1 = f2u2(bb[1], 0.f);
            u64 ac2 = f2u2(bb[2], 0.f), ac3 = f2u2(bb[3], 0.f);
            const ulonglong2* hq = (const ulonglong2*)hsm;
            #pragma unroll
            for (int q = 0; q < 10; q++) {
                ulonglong2 hv = hq[q];
                ac0 = fma2(w[0][2*q], hv.x, ac0); ac0 = fma2(w[0][2*q+1], hv.y, ac0);
                ac1 = fma2(w[1][2*q], hv.x, ac1); ac1 = fma2(w[1][2*q+1], hv.y, ac1);
                ac2 = fma2(w[2][2*q], hv.x, ac2); ac2 = fma2(w[2][2*q+1], hv.y, ac2);
                ac3 = fma2(w[3][2*q], hv.x, ac3); ac3 = fma2(w[3][2*q+1], hv.y, ac3);
            }
            float2 d0 = u2f2(ac0), d1 = u2f2(ac1), d2 = u2f2(ac2), d3 = u2f2(ac3);
            dots[lane]      = d0.x + d0.y;
            dots[lane + 32] = d1.x + d1.y;
            dots[lane + 64] = d2.x + d2.y;
            if (lane < 24) dots[lane + 96] = d3.x + d3.y;
            __syncwarp();
            // act phase
            {
                float r = sigf(a0r + dots[u0]);
                float z = sigf(a0z + dots[40 + u0]);
                float n = tanh_fast(fmaf(r, dots[80 + u0], a0n));
                h0 = fmaf(z, h0 - n, n);
                hsm[u0] = h0;
                outb[u0] = h0;
            }
            if (two) {
                float r = sigf(c0r + dots[u1]);
                float z = sigf(c0z + dots[40 + u1]);
                float n = tanh_fast(fmaf(r, dots[80 + u1], c0n));
                h1 = fmaf(z, h1 - n, n);
                hsm[u1] = h1;
                outb[u1] = h1;
            }
            outb += ostep;
            __syncwarp();
            a0r=a1r; a0z=a1z; a0n=a1n; a1r=a2r; a1z=a2z; a1n=a2n;
            c0r=c1r; c0z=c1z; c0n=c1n; c1r=c2r; c1z=c2z; c1n=c2n;
        }
        float* hl = dir ? g_hb0 : g_hf0;
        hl[b * HH + u0] = h0;
        if (two) hl[b * HH + u1] = h1;
    }
}

// ---------------- Layer 1: same shape, gx precomputed, fused pooling ----------------
__global__ void __launch_bounds__(128) gru_layer1(
    const int* __restrict__ lens,
    const float* __restrict__ bhh1f, const float* __restrict__ bhh1b)
{
    int wid = threadIdx.x >> 5, lane = threadIdx.x & 31;
    int wgid = blockIdx.x * 4 + wid;
    __shared__ float dots_s[4][128];
    __shared__ __align__(16) float h_s[4][48];
    if (wgid >= 512) return;
    float* dots = dots_s[wid];
    float* hsm = h_s[wid];

    for (int slot = 0; slot < 2; slot++) {
        int c = slot ? (1023 - wgid) : wgid;
        int b = g_perm[c >> 1];
        int dir = c & 1;
        int len = lens[b];

        u64 w[4][20];
        float bb[4];
        const u64* wp = (const u64*)g_Whh1P4 + (size_t)dir * 120 * 20;
        const float* bhh = dir ? bhh1b : bhh1f;
        #pragma unroll
        for (int m = 0; m < 4; m++) {
            int f = lane + 32 * m;
            if (f < 120) {
                const u64* wf = wp + f * 20;
                #pragma unroll
                for (int k2 = 0; k2 < 20; k2++) w[m][k2] = wf[k2];
                bb[m] = bhh[f];
            } else {
                #pragma unroll
                for (int k2 = 0; k2 < 20; k2++) w[m][k2] = 0ull;
                bb[m] = 0.f;
            }
        }
        hsm[lane] = 0.f;
        if (lane < 16) hsm[32 + lane] = 0.f;
        __syncwarp();

        int t0 = dir ? (len - 1) : 0;
        int td = dir ? -1 : 1;
        const float* gxb = g_gx1 + ((size_t)b * TT) * 240 + dir * 120;
        int u0 = lane;
        int u1 = 32 + lane;
        bool two = (lane < 8);

        float a0r=0,a0z=0,a0n=0,a1r=0,a1z=0,a1n=0;
        float c0r=0,c0z=0,c0n=0,c1r=0,c1z=0,c1n=0;
        {
            const float* e0 = gxb + (size_t)t0 * 240;
            a0r = e0[u0]; a0z = e0[40 + u0]; a0n = e0[80 + u0];
            if (two) { c0r = e0[u1]; c0z = e0[40 + u1]; c0n = e0[80 + u1]; }
            if (len > 1) {
                const float* e1 = gxb + (size_t)(t0 + td) * 240;
                a1r = e1[u0]; a1z = e1[40 + u0]; a1n = e1[80 + u0];
                if (two) { c1r = e1[u1]; c1z = e1[40 + u1]; c1n = e1[80 + u1]; }
            }
        }
        float h0 = 0.f, h1 = 0.f;
        float sum0 = 0.f, max0 = -1e30f, sum1 = 0.f, max1 = -1e30f;

        for (int s = 0; s < len; s++) {
            float a2r=0,a2z=0,a2n=0,c2r=0,c2z=0,c2n=0;
            if (s + 2 < len) {
                const float* e2 = gxb + (size_t)(t0 + (s + 2) * td) * 240;
                a2r = e2[u0]; a2z = e2[40 + u0]; a2n = e2[80 + u0];
                if (two) { c2r = e2[u1]; c2z = e2[40 + u1]; c2n = e2[80 + u1]; }
            }
            u64 ac0 = f2u2(bb[0], 0.f), ac1 = f2u2(bb[1], 0.f);
            u64 ac2 = f2u2(bb[2], 0.f), ac3 = f2u2(bb[3], 0.f);
            const ulonglong2* hq = (const ulonglong2*)hsm;
            #pragma unroll
            for (int q = 0; q < 10; q++) {
                ulonglong2 hv = hq[q];
                ac0 = fma2(w[0][2*q], hv.x, ac0); ac0 = fma2(w[0][2*q+1], hv.y, ac0);
                ac1 = fma2(w[1][2*q], hv.x, ac1); ac1 = fma2(w[1][2*q+1], hv.y, ac1);
                ac2 = fma2(w[2][2*q], hv.x, ac2); ac2 = fma2(w[2][2*q+1], hv.y, ac2);
                ac3 = fma2(w[3][2*q], hv.x, ac3); ac3 = fma2(w[3][2*q+1], hv.y, ac3);
            }
            float2 d0 = u2f2(ac0), d1 = u2f2(ac1), d2 = u2f2(ac2), d3 = u2f2(ac3);
            dots[lane]      = d0.x + d0.y;
            dots[lane + 32] = d1.x + d1.y;
            dots[lane + 64] = d2.x + d2.y;
            if (lane < 24) dots[lane + 96] = d3.x + d3.y;
            __syncwarp();
            {
                float r = sigf(a0r + dots[u0]);
                float z = sigf(a0z + dots[40 + u0]);
                float n = tanh_fast(fmaf(r, dots[80 + u0], a0n));
                h0 = fmaf(z, h0 - n, n);
                hsm[u0] = h0;
                sum0 += h0;
                max0 = fmaxf(max0, h0);
            }
            if (two) {
                float r = sigf(c0r + dots[u1]);
                float z = sigf(c0z + dots[40 + u1]);
                float n = tanh_fast(fmaf(r, dots[80 + u1], c0n));
                h1 = fmaf(z, h1 - n, n);
                hsm[u1] = h1;
                sum1 += h1;
                max1 = fmaxf(max1, h1);
            }
            __syncwarp();
            a0r=a1r; a0z=a1z; a0n=a1n; a1r=a2r; a1z=a2z; a1n=a2n;
            c0r=c1r; c0z=c1z; c0n=c1n; c1r=c2r; c1z=c2z; c1n=c2n;
        }
        float inv = __fdividef(1.f, (float)len);
        g_avgp[b * 80 + dir * 40 + u0] = sum0 * inv;
        g_maxp[b * 80 + dir * 40 + u0] = max0;
        float* hl = dir ? g_hb1 : g_hf1;
        hl[b * HH + u0] = h0;
        if (two) {
            g_avgp[b * 80 + dir * 40 + u1] = sum1 * inv;
            g_maxp[b * 80 + dir * 40 + u1] = max1;
            hl[b * HH + u1] = h1;
        }
    }
}

// ---------------- Head: pool_cat -> fc1 -> leaky -> fc2 ----------------
__global__ void __launch_bounds__(128) fc_kernel(
    const float* __restrict__ fc1_b, const float* __restrict__ fc2_W,
    const float* __restrict__ fc2_b, float* __restrict__ out)
{
    int b = blockIdx.x, j = threadIdx.x;
    __shared__ float cat[320];
    for (int i = j; i < 320; i += 128) {
        float v;
        if (i < 40)       v = g_hb1[b * 40 + i];
        else if (i < 80)  v = g_hf1[b * 40 + (i - 40)];
        else if (i < 120) v = g_hb0[b * 40 + (i - 80)];
        else if (i < 160) v = g_hf0[b * 40 + (i - 120)];
        else if (i < 240) v = g_avgp[b * 80 + (i - 160)];
        else              v = g_maxp[b * 80 + (i - 240)];
        cat[i] = v;
    }
    __syncthreads();
    float acc = fc1_b[j];
    #pragma unroll 8
    for (int k = 0; k < 320; k++)
        acc = fmaf(g_fc1WT[k * 128 + j], cat[k], acc);
    float h = (acc >= 0.f) ? acc : 0.01f * acc;
    float p = h * fc2_W[j];
    #pragma unroll
    for (int o = 16; o > 0; o >>= 1) p += __shfl_down_sync(0xffffffffu, p, o);
    __shared__ float red[4];
    if ((j & 31) == 0) red[j >> 5] = p;
    __syncthreads();
    if (j == 0) out[b] = (red[0] + red[1] + red[2] + red[3]) + fc2_b[0];
}

// ---------------- Launch ----------------
extern "C" void kernel_launch(void* const* d_in, const int* in_sizes, int n_in,
                              void* d_out, int out_size)
{
    const int*   text     = (const int*)d_in[0];
    const int*   text_len = (const int*)d_in[1];
    const float* emb      = (const float*)d_in[2];
    const float* Wih0f = (const float*)d_in[3];
    const float* Whh0f = (const float*)d_in[4];
    const float* bih0f = (const float*)d_in[5];
    const float* bhh0f = (const float*)d_in[6];
    const float* Wih0b = (const float*)d_in[7];
    const float* Whh0b = (const float*)d_in[8];
    const float* bih0b = (const float*)d_in[9];
    const float* bhh0b = (const float*)d_in[10];
    const float* Wih1f = (const float*)d_in[11];
    const float* Whh1f = (const float*)d_in[12];
    const float* bih1f = (const float*)d_in[13];
    const float* bhh1f = (const float*)d_in[14];
    const float* Wih1b = (const float*)d_in[15];
    const float* Whh1b = (const float*)d_in[16];
    const float* bih1b = (const float*)d_in[17];
    const float* bhh1b = (const float*)d_in[18];
    const float* fc1_W = (const float*)d_in[19];
    const float* fc1_b = (const float*)d_in[20];
    const float* fc2_W = (const float*)d_in[21];
    const float* fc2_b = (const float*)d_in[22];
    float* out = (float*)d_out;

    prep_weights<<<160, 256>>>(Wih0f, Whh0f, bih0f, Wih0b, Whh0b, bih0b,
                               Wih1f, Whh1f, bih1f, Wih1b, Whh1b, bih1b, fc1_W);
    sort_kernel<<<1, BB>>>(text_len);
    embw_kernel<<<(VV + 63) / 64, 256>>>(emb);
    gru_layer0<<<148, 128>>>(text, text_len, bhh0f, bhh0b);
    gx1_kernel<<<dim3(BB, TT / 64), 256>>>(text_len);
    gru_layer1<<<148, 128>>>(text_len, bhh1f, bhh1b);
    fc_kernel<<<BB, 128>>>(fc1_b, fc2_W, fc2_b, out);
}